// round 2
// baseline (speedup 1.0000x reference)
#include <cuda_runtime.h>
#include <math.h>

#define S   2048
#define DIN 256
#define DM  512
#define NB  4
#define H   8
#define DK  64
#define BH  32   // NB*H

// Scratch (static __device__ arrays: allocation-free per harness rules)
// Layout: g_Q/g_K/g_V[(b*512 + m)][s]  ==  head-major [n=b*8+h][c][s] since m=h*64+c
__device__ float g_Q[BH * DK * S];
__device__ float g_K[BH * DK * S];
__device__ float g_V[BH * DK * S];
__device__ float g_AO[NB * S * DM];          // attn_out in [B, S, DM] (torch-faithful scrambled view)
__device__ float g_scratch[NB * H * S * S];  // fallback if d_out doesn't include attn_w

// ---------------------------------------------------------------------------
// Kernel 1: fused QKV projection.  O[m,s] = sum_d W[m,d] * x[b,d,s] + bias[m]
// x is [B, DIN, S] so x_b is a ready-made [DIN x S] row-major matrix: coalesced.
// ---------------------------------------------------------------------------
__global__ __launch_bounds__(256) void qkv_kernel(
    const float* __restrict__ x,
    const float* __restrict__ Wq, const float* __restrict__ bq,
    const float* __restrict__ Wk, const float* __restrict__ bk,
    const float* __restrict__ Wv, const float* __restrict__ bv)
{
    const int s0 = blockIdx.x * 64;
    const int m0 = blockIdx.y * 64;
    const int b  = blockIdx.z;
    __shared__ float sX[16][64];      // [d][s]
    __shared__ float sW[3][64][16];   // [w][m][d]
    const int tid = threadIdx.x;
    const int tx = tid & 15, ty = tid >> 4;

    float acc[3][4][4];
#pragma unroll
    for (int w = 0; w < 3; w++)
#pragma unroll
        for (int i = 0; i < 4; i++)
#pragma unroll
            for (int j = 0; j < 4; j++) acc[w][i][j] = 0.f;

    for (int d0 = 0; d0 < DIN; d0 += 16) {
        {
            int dd = tid >> 4, sv = (tid & 15) * 4;
            *(float4*)&sX[dd][sv] =
                *(const float4*)(x + (size_t)(b * DIN + d0 + dd) * S + s0 + sv);
        }
        {
            int mm = tid >> 2, dv = (tid & 3) * 4;
            const int wofs = (m0 + mm) * DIN + d0 + dv;
            *(float4*)&sW[0][mm][dv] = *(const float4*)(Wq + wofs);
            *(float4*)&sW[1][mm][dv] = *(const float4*)(Wk + wofs);
            *(float4*)&sW[2][mm][dv] = *(const float4*)(Wv + wofs);
        }
        __syncthreads();
#pragma unroll
        for (int dd = 0; dd < 16; dd++) {
            float xb[4];
            *(float4*)xb = *(float4*)&sX[dd][tx * 4];
#pragma unroll
            for (int w = 0; w < 3; w++) {
                float wr[4];
#pragma unroll
                for (int i = 0; i < 4; i++) wr[i] = sW[w][ty * 4 + i][dd];
#pragma unroll
                for (int i = 0; i < 4; i++)
#pragma unroll
                    for (int j = 0; j < 4; j++) acc[w][i][j] += wr[i] * xb[j];
            }
        }
        __syncthreads();
    }

    float* outs[3]   = {g_Q, g_K, g_V};
    const float* bs[3] = {bq, bk, bv};
#pragma unroll
    for (int w = 0; w < 3; w++) {
#pragma unroll
        for (int i = 0; i < 4; i++) {
            int m = m0 + ty * 4 + i;
            float bb = bs[w][m];
            float4 r;
            r.x = acc[w][i][0] + bb;
            r.y = acc[w][i][1] + bb;
            r.z = acc[w][i][2] + bb;
            r.w = acc[w][i][3] + bb;
            *(float4*)(outs[w] + (size_t)(b * DM + m) * S + s0 + tx * 4) = r;
        }
    }
}

// ---------------------------------------------------------------------------
// Kernel 2: raw scores[n,q,k] = sum_c Q[n,c,q] * K[n,c,k]  (no 1/sqrt(dk)!)
// Written directly into the attn_w output region.
// ---------------------------------------------------------------------------
__global__ __launch_bounds__(256) void scores_kernel(float* __restrict__ attn)
{
    const int k0 = blockIdx.x * 64;
    const int q0 = blockIdx.y * 64;
    const int n  = blockIdx.z;
    __shared__ float sQ[64][64];  // [c][q]
    __shared__ float sK[64][64];  // [c][k]
    const int tid = threadIdx.x;
    const int tx = tid & 15, ty = tid >> 4;
    const float* Qb = g_Q + (size_t)n * DK * S;
    const float* Kb = g_K + (size_t)n * DK * S;
#pragma unroll
    for (int r = 0; r < 4; r++) {
        int c  = (tid >> 4) + r * 16;
        int ev = (tid & 15) * 4;
        *(float4*)&sQ[c][ev] = *(const float4*)(Qb + (size_t)c * S + q0 + ev);
        *(float4*)&sK[c][ev] = *(const float4*)(Kb + (size_t)c * S + k0 + ev);
    }
    __syncthreads();
    float acc[4][4] = {};
#pragma unroll
    for (int c = 0; c < 64; c++) {
        float a[4], bb[4];
        *(float4*)a  = *(float4*)&sQ[c][ty * 4];
        *(float4*)bb = *(float4*)&sK[c][tx * 4];
#pragma unroll
        for (int i = 0; i < 4; i++)
#pragma unroll
            for (int j = 0; j < 4; j++) acc[i][j] += a[i] * bb[j];
    }
    float* out = attn + ((size_t)n * S + q0) * S + k0;
#pragma unroll
    for (int i = 0; i < 4; i++)
        *(float4*)(out + (size_t)(ty * 4 + i) * S + tx * 4) = *(float4*)acc[i];
}

// ---------------------------------------------------------------------------
// Kernel 3: in-place row softmax over last dim (2048). One block per row.
// ---------------------------------------------------------------------------
__global__ __launch_bounds__(256) void softmax_kernel(float* __restrict__ attn)
{
    float* p = attn + (size_t)blockIdx.x * S;
    const int tid = threadIdx.x;
    __shared__ float red[8];

    float v[8];
    float mx = -1e30f;
#pragma unroll
    for (int i = 0; i < 8; i++) {
        v[i] = p[tid + i * 256];
        mx = fmaxf(mx, v[i]);
    }
#pragma unroll
    for (int o = 16; o; o >>= 1) mx = fmaxf(mx, __shfl_xor_sync(0xffffffffu, mx, o));
    if ((tid & 31) == 0) red[tid >> 5] = mx;
    __syncthreads();
    if (tid < 32) {
        float m2 = (tid < 8) ? red[tid] : -1e30f;
#pragma unroll
        for (int o = 4; o; o >>= 1) m2 = fmaxf(m2, __shfl_xor_sync(0xffffffffu, m2, o));
        if (tid == 0) red[0] = m2;
    }
    __syncthreads();
    mx = red[0];

    float sum = 0.f;
#pragma unroll
    for (int i = 0; i < 8; i++) {
        v[i] = expf(v[i] - mx);
        sum += v[i];
    }
    __syncthreads();  // red reuse
#pragma unroll
    for (int o = 16; o; o >>= 1) sum += __shfl_xor_sync(0xffffffffu, sum, o);
    if ((tid & 31) == 0) red[tid >> 5] = sum;
    __syncthreads();
    if (tid < 32) {
        float s2 = (tid < 8) ? red[tid] : 0.f;
#pragma unroll
        for (int o = 4; o; o >>= 1) s2 += __shfl_xor_sync(0xffffffffu, s2, o);
        if (tid == 0) red[0] = s2;
    }
    __syncthreads();
    float inv = 1.f / red[0];
#pragma unroll
    for (int i = 0; i < 8; i++) p[tid + i * 256] = v[i] * inv;
}

// ---------------------------------------------------------------------------
// Kernel 4: attn_out[n,q,c] = sum_k w[n,q,k] * V[n,c,k], scattered into the
// torch-faithful [B,S,DM] view: AO[q>>9][(q&511)*4 + (n>>3)][(n&7)*64 + c]
// ---------------------------------------------------------------------------
__global__ __launch_bounds__(256) void av_kernel(const float* __restrict__ attn)
{
    const int q0 = blockIdx.x * 64;
    const int n  = blockIdx.y;
    const int bb_ = n >> 3, hh = n & 7;
    __shared__ float sP[64][33];  // [q][k-chunk], +1 pad: conflict-free strided reads
    __shared__ float sV[64][33];  // [c][k-chunk]
    const int tid = threadIdx.x;
    const int tx = tid & 15, ty = tid >> 4;
    float acc[4][4] = {};
    const float* prow = attn + ((size_t)n * S + q0) * S;
    const float* vrow = g_V + (size_t)n * DK * S;

    for (int k0 = 0; k0 < S; k0 += 32) {
#pragma unroll
        for (int r = 0; r < 2; r++) {
            int row = (tid >> 3) + r * 32;
            int cv  = (tid & 7) * 4;
            float4 pv = *(const float4*)(prow + (size_t)row * S + k0 + cv);
            float4 vv = *(const float4*)(vrow + (size_t)row * S + k0 + cv);
            sP[row][cv] = pv.x; sP[row][cv + 1] = pv.y; sP[row][cv + 2] = pv.z; sP[row][cv + 3] = pv.w;
            sV[row][cv] = vv.x; sV[row][cv + 1] = vv.y; sV[row][cv + 2] = vv.z; sV[row][cv + 3] = vv.w;
        }
        __syncthreads();
#pragma unroll
        for (int kk = 0; kk < 32; kk++) {
            float a[4], c4[4];
#pragma unroll
            for (int i = 0; i < 4; i++) { a[i] = sP[ty * 4 + i][kk]; c4[i] = sV[tx * 4 + i][kk]; }
#pragma unroll
            for (int i = 0; i < 4; i++)
#pragma unroll
                for (int j = 0; j < 4; j++) acc[i][j] += a[i] * c4[j];
        }
        __syncthreads();
    }
#pragma unroll
    for (int i = 0; i < 4; i++) {
        int q  = q0 + ty * 4 + i;
        int bp = q >> 9;
        int sp = ((q & 511) << 2) + bb_;
        float4 r;
        r.x = acc[i][0]; r.y = acc[i][1]; r.z = acc[i][2]; r.w = acc[i][3];
        *(float4*)(g_AO + ((size_t)bp * S + sp) * DM + hh * DK + tx * 4) = r;
    }
}

// ---------------------------------------------------------------------------
// Kernel 5: Z[bp,d,s] = sum_m Wo[d,m] * AO[bp,s,m] + bo[d]
// ---------------------------------------------------------------------------
__global__ __launch_bounds__(256) void proj_kernel(
    const float* __restrict__ Wo, const float* __restrict__ bo, float* __restrict__ Z)
{
    const int s0 = blockIdx.x * 64;
    const int d0 = blockIdx.y * 64;
    const int bp = blockIdx.z;
    __shared__ float sW[64][33];  // [d][m-chunk]
    __shared__ float sA[64][33];  // [s][m-chunk]
    const int tid = threadIdx.x;
    const int tx = tid & 15, ty = tid >> 4;
    float acc[4][4] = {};

    for (int m0 = 0; m0 < DM; m0 += 32) {
#pragma unroll
        for (int r = 0; r < 2; r++) {
            int row = (tid >> 3) + r * 32;
            int cv  = (tid & 7) * 4;
            float4 w4 = *(const float4*)(Wo + (size_t)(d0 + row) * DM + m0 + cv);
            float4 a4 = *(const float4*)(g_AO + ((size_t)bp * S + s0 + row) * DM + m0 + cv);
            sW[row][cv] = w4.x; sW[row][cv + 1] = w4.y; sW[row][cv + 2] = w4.z; sW[row][cv + 3] = w4.w;
            sA[row][cv] = a4.x; sA[row][cv + 1] = a4.y; sA[row][cv + 2] = a4.z; sA[row][cv + 3] = a4.w;
        }
        __syncthreads();
#pragma unroll
        for (int kk = 0; kk < 32; kk++) {
            float a[4], c4[4];
#pragma unroll
            for (int i = 0; i < 4; i++) { a[i] = sW[ty * 4 + i][kk]; c4[i] = sA[tx * 4 + i][kk]; }
#pragma unroll
            for (int i = 0; i < 4; i++)
#pragma unroll
                for (int j = 0; j < 4; j++) acc[i][j] += a[i] * c4[j];
        }
        __syncthreads();
    }
#pragma unroll
    for (int i = 0; i < 4; i++) {
        int d = d0 + ty * 4 + i;
        float bias = bo[d];
        float4 r;
        r.x = acc[i][0] + bias; r.y = acc[i][1] + bias;
        r.z = acc[i][2] + bias; r.w = acc[i][3] + bias;
        *(float4*)(Z + (size_t)(bp * DIN + d) * S + s0 + tx * 4) = r;
    }
}

// ---------------------------------------------------------------------------
extern "C" void kernel_launch(void* const* d_in, const int* in_sizes, int n_in,
                              void* d_out, int out_size)
{
    const float* x  = (const float*)d_in[0];
    const float* Wq = (const float*)d_in[1];
    const float* bq = (const float*)d_in[2];
    const float* Wk = (const float*)d_in[3];
    const float* bk = (const float*)d_in[4];
    const float* Wv = (const float*)d_in[5];
    const float* bv = (const float*)d_in[6];
    const float* Wo = (const float*)d_in[7];
    const float* bo = (const float*)d_in[8];
    float* out = (float*)d_out;

    const long long zsz = (long long)NB * DIN * S;          // 2,097,152
    const long long asz = (long long)NB * H * S * S;        // 134,217,728
    float* attn;
    if ((long long)out_size >= zsz + asz) {
        attn = out + zsz;  // reference returns (Z, attn_w) -> concat layout
    } else {
        void* p = nullptr;
        cudaGetSymbolAddress(&p, g_scratch);
        attn = (float*)p;
    }

    qkv_kernel<<<dim3(S / 64, DM / 64, NB), 256>>>(x, Wq, bq, Wk, bk, Wv, bv);
    scores_kernel<<<dim3(S / 64, S / 64, BH), 256>>>(attn);
    softmax_kernel<<<BH * S, 256>>>(attn);
    av_kernel<<<dim3(S / 64, BH), 256>>>(attn);
    proj_kernel<<<dim3(S / 64, DIN / 64, NB), 256>>>(Wo, bo, out);
}

// round 3
// speedup vs baseline: 1.0024x; 1.0024x over previous
#include <cuda_runtime.h>
#include <math.h>

#define S   2048
#define DIN 256
#define DM  512
#define NB  4
#define H   8
#define DK  64
#define BH  32   // NB*H

// Scratch (static __device__ arrays: allocation-free per harness rules)
// Layout: g_Q/g_K/g_V[(b*512 + m)][s]  ==  head-major [n=b*8+h][c][s] since m=h*64+c
__device__ float g_Q[BH * DK * S];
__device__ float g_K[BH * DK * S];
__device__ float g_V[BH * DK * S];
__device__ float g_AO[NB * S * DM];          // attn_out in [B, S, DM] (torch-faithful scrambled view)
__device__ float g_scratch[NB * H * S * S];  // fallback if d_out doesn't include attn_w

// ---------------------------------------------------------------------------
// Kernel 1: fused QKV projection.  O[m,s] = sum_d W[m,d] * x[b,d,s] + bias[m]
// x is [B, DIN, S] so x_b is a ready-made [DIN x S] row-major matrix: coalesced.
// ---------------------------------------------------------------------------
__global__ __launch_bounds__(256) void qkv_kernel(
    const float* __restrict__ x,
    const float* __restrict__ Wq, const float* __restrict__ bq,
    const float* __restrict__ Wk, const float* __restrict__ bk,
    const float* __restrict__ Wv, const float* __restrict__ bv)
{
    const int s0 = blockIdx.x * 64;
    const int m0 = blockIdx.y * 64;
    const int b  = blockIdx.z;
    __shared__ float sX[16][64];      // [d][s]
    __shared__ float sW[3][64][16];   // [w][m][d]
    const int tid = threadIdx.x;
    const int tx = tid & 15, ty = tid >> 4;

    float acc[3][4][4];
#pragma unroll
    for (int w = 0; w < 3; w++)
#pragma unroll
        for (int i = 0; i < 4; i++)
#pragma unroll
            for (int j = 0; j < 4; j++) acc[w][i][j] = 0.f;

    for (int d0 = 0; d0 < DIN; d0 += 16) {
        {
            int dd = tid >> 4, sv = (tid & 15) * 4;
            *(float4*)&sX[dd][sv] =
                *(const float4*)(x + (size_t)(b * DIN + d0 + dd) * S + s0 + sv);
        }
        {
            int mm = tid >> 2, dv = (tid & 3) * 4;
            const int wofs = (m0 + mm) * DIN + d0 + dv;
            *(float4*)&sW[0][mm][dv] = *(const float4*)(Wq + wofs);
            *(float4*)&sW[1][mm][dv] = *(const float4*)(Wk + wofs);
            *(float4*)&sW[2][mm][dv] = *(const float4*)(Wv + wofs);
        }
        __syncthreads();
#pragma unroll
        for (int dd = 0; dd < 16; dd++) {
            float xb[4];
            *(float4*)xb = *(float4*)&sX[dd][tx * 4];
#pragma unroll
            for (int w = 0; w < 3; w++) {
                float wr[4];
#pragma unroll
                for (int i = 0; i < 4; i++) wr[i] = sW[w][ty * 4 + i][dd];
#pragma unroll
                for (int i = 0; i < 4; i++)
#pragma unroll
                    for (int j = 0; j < 4; j++) acc[w][i][j] += wr[i] * xb[j];
            }
        }
        __syncthreads();
    }

    float* outs[3]   = {g_Q, g_K, g_V};
    const float* bs[3] = {bq, bk, bv};
#pragma unroll
    for (int w = 0; w < 3; w++) {
#pragma unroll
        for (int i = 0; i < 4; i++) {
            int m = m0 + ty * 4 + i;
            float bb = bs[w][m];
            float4 r;
            r.x = acc[w][i][0] + bb;
            r.y = acc[w][i][1] + bb;
            r.z = acc[w][i][2] + bb;
            r.w = acc[w][i][3] + bb;
            *(float4*)(outs[w] + (size_t)(b * DM + m) * S + s0 + tx * 4) = r;
        }
    }
}

// ---------------------------------------------------------------------------
// Kernel 2: raw scores[n,q,k] = sum_c Q[n,c,q] * K[n,c,k]  (no 1/sqrt(dk)!)
// Written directly into the attn_w output region.
// ---------------------------------------------------------------------------
__global__ __launch_bounds__(256) void scores_kernel(float* __restrict__ attn)
{
    const int k0 = blockIdx.x * 64;
    const int q0 = blockIdx.y * 64;
    const int n  = blockIdx.z;
    __shared__ float sQ[64][64];  // [c][q]
    __shared__ float sK[64][64];  // [c][k]
    const int tid = threadIdx.x;
    const int tx = tid & 15, ty = tid >> 4;
    const float* Qb = g_Q + (size_t)n * DK * S;
    const float* Kb = g_K + (size_t)n * DK * S;
#pragma unroll
    for (int r = 0; r < 4; r++) {
        int c  = (tid >> 4) + r * 16;
        int ev = (tid & 15) * 4;
        *(float4*)&sQ[c][ev] = *(const float4*)(Qb + (size_t)c * S + q0 + ev);
        *(float4*)&sK[c][ev] = *(const float4*)(Kb + (size_t)c * S + k0 + ev);
    }
    __syncthreads();
    float acc[4][4] = {};
#pragma unroll
    for (int c = 0; c < 64; c++) {
        float a[4], bb[4];
        *(float4*)a  = *(float4*)&sQ[c][ty * 4];
        *(float4*)bb = *(float4*)&sK[c][tx * 4];
#pragma unroll
        for (int i = 0; i < 4; i++)
#pragma unroll
            for (int j = 0; j < 4; j++) acc[i][j] += a[i] * bb[j];
    }
    float* out = attn + ((size_t)n * S + q0) * S + k0;
#pragma unroll
    for (int i = 0; i < 4; i++)
        *(float4*)(out + (size_t)(ty * 4 + i) * S + tx * 4) = *(float4*)acc[i];
}

// ---------------------------------------------------------------------------
// Kernel 3: in-place row softmax over last dim (2048). One block per row.
// ---------------------------------------------------------------------------
__global__ __launch_bounds__(256) void softmax_kernel(float* __restrict__ attn)
{
    float* p = attn + (size_t)blockIdx.x * S;
    const int tid = threadIdx.x;
    __shared__ float red[8];

    float v[8];
    float mx = -1e30f;
#pragma unroll
    for (int i = 0; i < 8; i++) {
        v[i] = p[tid + i * 256];
        mx = fmaxf(mx, v[i]);
    }
#pragma unroll
    for (int o = 16; o; o >>= 1) mx = fmaxf(mx, __shfl_xor_sync(0xffffffffu, mx, o));
    if ((tid & 31) == 0) red[tid >> 5] = mx;
    __syncthreads();
    if (tid < 32) {
        float m2 = (tid < 8) ? red[tid] : -1e30f;
#pragma unroll
        for (int o = 4; o; o >>= 1) m2 = fmaxf(m2, __shfl_xor_sync(0xffffffffu, m2, o));
        if (tid == 0) red[0] = m2;
    }
    __syncthreads();
    mx = red[0];

    float sum = 0.f;
#pragma unroll
    for (int i = 0; i < 8; i++) {
        v[i] = expf(v[i] - mx);
        sum += v[i];
    }
    __syncthreads();  // red reuse
#pragma unroll
    for (int o = 16; o; o >>= 1) sum += __shfl_xor_sync(0xffffffffu, sum, o);
    if ((tid & 31) == 0) red[tid >> 5] = sum;
    __syncthreads();
    if (tid < 32) {
        float s2 = (tid < 8) ? red[tid] : 0.f;
#pragma unroll
        for (int o = 4; o; o >>= 1) s2 += __shfl_xor_sync(0xffffffffu, s2, o);
        if (tid == 0) red[0] = s2;
    }
    __syncthreads();
    float inv = 1.f / red[0];
#pragma unroll
    for (int i = 0; i < 8; i++) p[tid + i * 256] = v[i] * inv;
}

// ---------------------------------------------------------------------------
// Kernel 4: attn_out[n,q,c] = sum_k w[n,q,k] * V[n,c,k], scattered into the
// torch-faithful [B,S,DM] view: AO[q>>9][(q&511)*4 + (n>>3)][(n&7)*64 + c]
// ---------------------------------------------------------------------------
__global__ __launch_bounds__(256) void av_kernel(const float* __restrict__ attn)
{
    const int q0 = blockIdx.x * 64;
    const int n  = blockIdx.y;
    const int bb_ = n >> 3, hh = n & 7;
    __shared__ float sP[64][33];  // [q][k-chunk], +1 pad: conflict-free strided reads
    __shared__ float sV[64][33];  // [c][k-chunk]
    const int tid = threadIdx.x;
    const int tx = tid & 15, ty = tid >> 4;
    float acc[4][4] = {};
    const float* prow = attn + ((size_t)n * S + q0) * S;
    const float* vrow = g_V + (size_t)n * DK * S;

    for (int k0 = 0; k0 < S; k0 += 32) {
#pragma unroll
        for (int r = 0; r < 2; r++) {
            int row = (tid >> 3) + r * 32;
            int cv  = (tid & 7) * 4;
            float4 pv = *(const float4*)(prow + (size_t)row * S + k0 + cv);
            float4 vv = *(const float4*)(vrow + (size_t)row * S + k0 + cv);
            sP[row][cv] = pv.x; sP[row][cv + 1] = pv.y; sP[row][cv + 2] = pv.z; sP[row][cv + 3] = pv.w;
            sV[row][cv] = vv.x; sV[row][cv + 1] = vv.y; sV[row][cv + 2] = vv.z; sV[row][cv + 3] = vv.w;
        }
        __syncthreads();
#pragma unroll
        for (int kk = 0; kk < 32; kk++) {
            float a[4], c4[4];
#pragma unroll
            for (int i = 0; i < 4; i++) { a[i] = sP[ty * 4 + i][kk]; c4[i] = sV[tx * 4 + i][kk]; }
#pragma unroll
            for (int i = 0; i < 4; i++)
#pragma unroll
                for (int j = 0; j < 4; j++) acc[i][j] += a[i] * c4[j];
        }
        __syncthreads();
    }
#pragma unroll
    for (int i = 0; i < 4; i++) {
        int q  = q0 + ty * 4 + i;
        int bp = q >> 9;
        int sp = ((q & 511) << 2) + bb_;
        float4 r;
        r.x = acc[i][0]; r.y = acc[i][1]; r.z = acc[i][2]; r.w = acc[i][3];
        *(float4*)(g_AO + ((size_t)bp * S + sp) * DM + hh * DK + tx * 4) = r;
    }
}

// ---------------------------------------------------------------------------
// Kernel 5: Z[bp,d,s] = sum_m Wo[d,m] * AO[bp,s,m] + bo[d]
// ---------------------------------------------------------------------------
__global__ __launch_bounds__(256) void proj_kernel(
    const float* __restrict__ Wo, const float* __restrict__ bo, float* __restrict__ Z)
{
    const int s0 = blockIdx.x * 64;
    const int d0 = blockIdx.y * 64;
    const int bp = blockIdx.z;
    __shared__ float sW[64][33];  // [d][m-chunk]
    __shared__ float sA[64][33];  // [s][m-chunk]
    const int tid = threadIdx.x;
    const int tx = tid & 15, ty = tid >> 4;
    float acc[4][4] = {};

    for (int m0 = 0; m0 < DM; m0 += 32) {
#pragma unroll
        for (int r = 0; r < 2; r++) {
            int row = (tid >> 3) + r * 32;
            int cv  = (tid & 7) * 4;
            float4 w4 = *(const float4*)(Wo + (size_t)(d0 + row) * DM + m0 + cv);
            float4 a4 = *(const float4*)(g_AO + ((size_t)bp * S + s0 + row) * DM + m0 + cv);
            sW[row][cv] = w4.x; sW[row][cv + 1] = w4.y; sW[row][cv + 2] = w4.z; sW[row][cv + 3] = w4.w;
            sA[row][cv] = a4.x; sA[row][cv + 1] = a4.y; sA[row][cv + 2] = a4.z; sA[row][cv + 3] = a4.w;
        }
        __syncthreads();
#pragma unroll
        for (int kk = 0; kk < 32; kk++) {
            float a[4], c4[4];
#pragma unroll
            for (int i = 0; i < 4; i++) { a[i] = sW[ty * 4 + i][kk]; c4[i] = sA[tx * 4 + i][kk]; }
#pragma unroll
            for (int i = 0; i < 4; i++)
#pragma unroll
                for (int j = 0; j < 4; j++) acc[i][j] += a[i] * c4[j];
        }
        __syncthreads();
    }
#pragma unroll
    for (int i = 0; i < 4; i++) {
        int d = d0 + ty * 4 + i;
        float bias = bo[d];
        float4 r;
        r.x = acc[i][0] + bias; r.y = acc[i][1] + bias;
        r.z = acc[i][2] + bias; r.w = acc[i][3] + bias;
        *(float4*)(Z + (size_t)(bp * DIN + d) * S + s0 + tx * 4) = r;
    }
}

// ---------------------------------------------------------------------------
extern "C" void kernel_launch(void* const* d_in, const int* in_sizes, int n_in,
                              void* d_out, int out_size)
{
    const float* x  = (const float*)d_in[0];
    const float* Wq = (const float*)d_in[1];
    const float* bq = (const float*)d_in[2];
    const float* Wk = (const float*)d_in[3];
    const float* bk = (const float*)d_in[4];
    const float* Wv = (const float*)d_in[5];
    const float* bv = (const float*)d_in[6];
    const float* Wo = (const float*)d_in[7];
    const float* bo = (const float*)d_in[8];
    float* out = (float*)d_out;

    const long long zsz = (long long)NB * DIN * S;          // 2,097,152
    const long long asz = (long long)NB * H * S * S;        // 134,217,728
    float* attn;
    if ((long long)out_size >= zsz + asz) {
        attn = out + zsz;  // reference returns (Z, attn_w) -> concat layout
    } else {
        void* p = nullptr;
        cudaGetSymbolAddress(&p, g_scratch);
        attn = (float*)p;
    }

    qkv_kernel<<<dim3(S / 64, DM / 64, NB), 256>>>(x, Wq, bq, Wk, bk, Wv, bv);
    scores_kernel<<<dim3(S / 64, S / 64, BH), 256>>>(attn);
    softmax_kernel<<<BH * S, 256>>>(attn);
    av_kernel<<<dim3(S / 64, BH), 256>>>(attn);
    proj_kernel<<<dim3(S / 64, DIN / 64, NB), 256>>>(Wo, bo, out);
}

// round 5
// speedup vs baseline: 1.2535x; 1.2505x over previous
#include <cuda_runtime.h>
#include <cuda_bf16.h>
#include <stdint.h>
#include <math.h>

#define S   2048
#define DIN 256
#define DM  512
#define NB  4
#define H   8
#define DK  64
#define BH  32

__device__ __nv_bfloat16 g_Qc[(size_t)BH * S * 128];   // [n][s][hi(64)|lo(64)]
__device__ __nv_bfloat16 g_Kc[(size_t)BH * S * 128];
__device__ __nv_bfloat16 g_Vhi[(size_t)BH * DK * S];   // [n][c][s]
__device__ __nv_bfloat16 g_Vlo[(size_t)BH * DK * S];
__device__ float g_part[(size_t)BH * S * 32];          // [row][ktile*2+wn]
__device__ float g_inv[(size_t)BH * S];
__device__ float g_AO[(size_t)NB * S * DM];
__device__ float g_scratch[(size_t)NB * H * S * S];

__device__ __forceinline__ uint32_t smem_u32(const void* p) {
    uint32_t a;
    asm("{ .reg .u64 t; cvta.to.shared.u64 t, %1; cvt.u32.u64 %0, t; }" : "=r"(a) : "l"(p));
    return a;
}
__device__ __forceinline__ void ldsm4(uint32_t addr, uint32_t& r0, uint32_t& r1,
                                      uint32_t& r2, uint32_t& r3) {
    asm volatile("ldmatrix.sync.aligned.m8n8.x4.shared.b16 {%0,%1,%2,%3}, [%4];"
                 : "=r"(r0), "=r"(r1), "=r"(r2), "=r"(r3) : "r"(addr));
}
__device__ __forceinline__ void mma16816(float* c, const uint32_t* a, uint32_t b0, uint32_t b1) {
    asm volatile(
        "mma.sync.aligned.m16n8k16.row.col.f32.bf16.bf16.f32 "
        "{%0,%1,%2,%3},{%4,%5,%6,%7},{%8,%9},{%0,%1,%2,%3};"
        : "+f"(c[0]), "+f"(c[1]), "+f"(c[2]), "+f"(c[3])
        : "r"(a[0]), "r"(a[1]), "r"(a[2]), "r"(a[3]), "r"(b0), "r"(b1));
}

// ---------------------------------------------------------------------------
// K1: QKV projection (fp32 SIMT) + bf16 hi/lo emission
// ---------------------------------------------------------------------------
__global__ __launch_bounds__(256) void qkv_kernel(
    const float* __restrict__ x,
    const float* __restrict__ Wq, const float* __restrict__ bq,
    const float* __restrict__ Wk, const float* __restrict__ bk,
    const float* __restrict__ Wv, const float* __restrict__ bv)
{
    const int s0 = blockIdx.x * 64, m0 = blockIdx.y * 64, b = blockIdx.z;
    __shared__ float sX[16][64];
    __shared__ float sW[3][64][16];
    const int tid = threadIdx.x, tx = tid & 15, ty = tid >> 4;
    float acc[3][4][4];
#pragma unroll
    for (int w = 0; w < 3; w++)
#pragma unroll
        for (int i = 0; i < 4; i++)
#pragma unroll
            for (int j = 0; j < 4; j++) acc[w][i][j] = 0.f;

    for (int d0 = 0; d0 < DIN; d0 += 16) {
        {
            int dd = tid >> 4, sv = (tid & 15) * 4;
            *(float4*)&sX[dd][sv] = *(const float4*)(x + (size_t)(b * DIN + d0 + dd) * S + s0 + sv);
        }
        {
            int mm = tid >> 2, dv = (tid & 3) * 4;
            const int wofs = (m0 + mm) * DIN + d0 + dv;
            *(float4*)&sW[0][mm][dv] = *(const float4*)(Wq + wofs);
            *(float4*)&sW[1][mm][dv] = *(const float4*)(Wk + wofs);
            *(float4*)&sW[2][mm][dv] = *(const float4*)(Wv + wofs);
        }
        __syncthreads();
#pragma unroll
        for (int dd = 0; dd < 16; dd++) {
            float xb[4];
            *(float4*)xb = *(float4*)&sX[dd][tx * 4];
#pragma unroll
            for (int w = 0; w < 3; w++) {
                float wr[4];
#pragma unroll
                for (int i = 0; i < 4; i++) wr[i] = sW[w][ty * 4 + i][dd];
#pragma unroll
                for (int i = 0; i < 4; i++)
#pragma unroll
                    for (int j = 0; j < 4; j++) acc[w][i][j] += wr[i] * xb[j];
            }
        }
        __syncthreads();
    }

    const int n = b * 8 + (m0 >> 6);
    const float* bs[3] = {bq, bk, bv};
#pragma unroll
    for (int w = 0; w < 3; w++) {
        float v[4][4];
#pragma unroll
        for (int i = 0; i < 4; i++) {
            float bb = bs[w][m0 + ty * 4 + i];
#pragma unroll
            for (int j = 0; j < 4; j++) v[i][j] = acc[w][i][j] + bb;
        }
        if (w < 2) {
            __nv_bfloat16* dst = (w == 0) ? g_Qc : g_Kc;
#pragma unroll
            for (int j = 0; j < 4; j++) {
                __align__(8) __nv_bfloat16 hi[4], lo[4];
#pragma unroll
                for (int i = 0; i < 4; i++) {
                    float p = v[i][j];
                    hi[i] = __float2bfloat16(p);
                    lo[i] = __float2bfloat16(p - __bfloat162float(hi[i]));
                }
                size_t off = ((size_t)n * S + s0 + tx * 4 + j) * 128 + ty * 4;
                *(uint2*)(dst + off) = *(uint2*)hi;
                *(uint2*)(dst + off + 64) = *(uint2*)lo;
            }
        } else {
#pragma unroll
            for (int i = 0; i < 4; i++) {
                __align__(8) __nv_bfloat16 hi[4], lo[4];
#pragma unroll
                for (int j = 0; j < 4; j++) {
                    float p = v[i][j];
                    hi[j] = __float2bfloat16(p);
                    lo[j] = __float2bfloat16(p - __bfloat162float(hi[j]));
                }
                size_t off = ((size_t)n * DK + ty * 4 + i) * S + s0 + tx * 4;
                *(uint2*)(g_Vhi + off) = *(uint2*)hi;
                *(uint2*)(g_Vlo + off) = *(uint2*)lo;
            }
        }
    }
}

// ---------------------------------------------------------------------------
// K2: scores via mma.sync hi/lo (3 products). Writes exp(S) + partial rowsums.
// CTA: 128q x 128k tile; 8 warps, warp = 32q x 64k (2 m-frags x 8 n-frags).
// ---------------------------------------------------------------------------
#define PAD 72   // padded row length (bf16 elems): 144B stride, conflict-free ldmatrix
__global__ __launch_bounds__(256) void score_kernel(float* __restrict__ attn)
{
    extern __shared__ char smp[];
    __nv_bfloat16* sQh = (__nv_bfloat16*)smp;       // [128][PAD]
    __nv_bfloat16* sQl = sQh + 128 * PAD;
    __nv_bfloat16* sKh = sQl + 128 * PAD;
    __nv_bfloat16* sKl = sKh + 128 * PAD;
    const int kb = blockIdx.x * 128, qb = blockIdx.y * 128, n = blockIdx.z;
    const int tid = threadIdx.x, wid = tid >> 5, lane = tid & 31;
    const int wm = wid >> 1, wn = wid & 1;

    const __nv_bfloat16* Qg = g_Qc + ((size_t)n * S + qb) * 128;
    const __nv_bfloat16* Kg = g_Kc + ((size_t)n * S + kb) * 128;
    for (int u = tid; u < 2048; u += 256) {
        int row = u >> 4, ch = u & 15;
        __nv_bfloat16* dq = (ch < 8 ? sQh : sQl) + row * PAD + (ch & 7) * 8;
        __nv_bfloat16* dk = (ch < 8 ? sKh : sKl) + row * PAD + (ch & 7) * 8;
        *(uint4*)dq = *(const uint4*)(Qg + row * 128 + ch * 8);
        *(uint4*)dk = *(const uint4*)(Kg + row * 128 + ch * 8);
    }
    __syncthreads();

    float acc[16][4];
#pragma unroll
    for (int f = 0; f < 16; f++)
#pragma unroll
        for (int e = 0; e < 4; e++) acc[f][e] = 0.f;

    const uint32_t uQh = smem_u32(sQh), uQl = smem_u32(sQl);
    const uint32_t uKh = smem_u32(sKh), uKl = smem_u32(sKl);
    const int arow = wm * 32 + (lane & 15);
    const int acol8 = (lane >> 4) << 3;
    const int brow = wn * 64 + (lane & 7) + ((lane >> 4) << 3);
    const int bcol8 = ((lane >> 3) & 1) << 3;

#pragma unroll
    for (int ks = 0; ks < 4; ks++) {
        const int k0 = ks * 16;
        uint32_t ah[2][4], al[2][4];
#pragma unroll
        for (int mf = 0; mf < 2; mf++) {
            uint32_t off = (uint32_t)((arow + mf * 16) * PAD + k0 + acol8) * 2;
            ldsm4(uQh + off, ah[mf][0], ah[mf][1], ah[mf][2], ah[mf][3]);
            ldsm4(uQl + off, al[mf][0], al[mf][1], al[mf][2], al[mf][3]);
        }
#pragma unroll
        for (int nf2 = 0; nf2 < 4; nf2++) {
            uint32_t boff = (uint32_t)((brow + nf2 * 16) * PAD + k0 + bcol8) * 2;
            uint32_t bh[4], bl[4];
            ldsm4(uKh + boff, bh[0], bh[1], bh[2], bh[3]);
            ldsm4(uKl + boff, bl[0], bl[1], bl[2], bl[3]);
#pragma unroll
            for (int mf = 0; mf < 2; mf++) {
                float* c0 = acc[mf * 8 + nf2 * 2];
                float* c1 = acc[mf * 8 + nf2 * 2 + 1];
                mma16816(c0, ah[mf], bh[0], bh[1]);
                mma16816(c0, al[mf], bh[0], bh[1]);
                mma16816(c0, ah[mf], bl[0], bl[1]);
                mma16816(c1, ah[mf], bh[2], bh[3]);
                mma16816(c1, al[mf], bh[2], bh[3]);
                mma16816(c1, ah[mf], bl[2], bl[3]);
            }
        }
    }
    __syncthreads();

    // epilogue: exp + partial rowsums + staged coalesced store
    float* sS = (float*)smp;  // [128][132]
    const int g = lane >> 2, c = lane & 3;
    float rsum[4] = {0.f, 0.f, 0.f, 0.f};
#pragma unroll
    for (int mf = 0; mf < 2; mf++)
#pragma unroll
        for (int nf = 0; nf < 8; nf++) {
            float* a = acc[mf * 8 + nf];
            int r0 = wm * 32 + mf * 16 + g, col = wn * 64 + nf * 8 + c * 2;
            float e0 = __expf(a[0]), e1 = __expf(a[1]);
            float e2 = __expf(a[2]), e3 = __expf(a[3]);
            sS[r0 * 132 + col] = e0;       sS[r0 * 132 + col + 1] = e1;
            sS[(r0 + 8) * 132 + col] = e2; sS[(r0 + 8) * 132 + col + 1] = e3;
            rsum[mf * 2] += e0 + e1;
            rsum[mf * 2 + 1] += e2 + e3;
        }
#pragma unroll
    for (int off = 1; off <= 2; off <<= 1)
#pragma unroll
        for (int i = 0; i < 4; i++) rsum[i] += __shfl_xor_sync(0xffffffffu, rsum[i], off);
    if (c == 0) {
#pragma unroll
        for (int mf = 0; mf < 2; mf++)
#pragma unroll
            for (int hh = 0; hh < 2; hh++) {
                int r = wm * 32 + mf * 16 + g + hh * 8;
                g_part[((size_t)n * S + qb + r) * 32 + blockIdx.x * 2 + wn] = rsum[mf * 2 + hh];
            }
    }
    __syncthreads();
    for (int it = tid; it < 4096; it += 256) {
        int row = it >> 5, c4 = it & 31;
        *(float4*)(attn + ((size_t)n * S + qb + row) * S + kb + c4 * 4) =
            *(float4*)(sS + row * 132 + c4 * 4);
    }
}

// ---------------------------------------------------------------------------
// K3: rowsum reduce -> inverse
// ---------------------------------------------------------------------------
__global__ __launch_bounds__(256) void reduce_kernel()
{
    int row = blockIdx.x * 256 + threadIdx.x;
    const float* p = g_part + (size_t)row * 32;
    float s = 0.f;
#pragma unroll
    for (int i = 0; i < 32; i++) s += p[i];
    g_inv[row] = 1.f / s;
}

// ---------------------------------------------------------------------------
// K4: normalize E (write final attn_w) + mma.sync AV hi/lo + scatter O.
// CTA: 128q x 64c, k-chunks of 64; 8 warps, warp = 32q x 32c.
// ---------------------------------------------------------------------------
__global__ __launch_bounds__(256) void av_kernel(float* __restrict__ attn)
{
    extern __shared__ char smp[];
    __nv_bfloat16* sPh = (__nv_bfloat16*)smp;        // [128][PAD]
    __nv_bfloat16* sPl = sPh + 128 * PAD;
    __nv_bfloat16* sVh = sPl + 128 * PAD;            // [64][PAD]
    __nv_bfloat16* sVl = sVh + 64 * PAD;
    __shared__ float sInv[128];
    const int qb = blockIdx.x * 128, n = blockIdx.y;
    const int tid = threadIdx.x, wid = tid >> 5, lane = tid & 31;
    const int wm = wid >> 1, wn = wid & 1;
    if (tid < 128) sInv[tid] = g_inv[(size_t)n * S + qb + tid];
    __syncthreads();

    float acc[8][4];
#pragma unroll
    for (int f = 0; f < 8; f++)
#pragma unroll
        for (int e = 0; e < 4; e++) acc[f][e] = 0.f;

    const uint32_t uPh = smem_u32(sPh), uPl = smem_u32(sPl);
    const uint32_t uVh = smem_u32(sVh), uVl = smem_u32(sVl);
    const int arow = wm * 32 + (lane & 15);
    const int acol8 = (lane >> 4) << 3;
    const int brow = wn * 32 + (lane & 7) + ((lane >> 4) << 3);
    const int bcol8 = ((lane >> 3) & 1) << 3;

    for (int kc = 0; kc < 32; kc++) {
        const int k0g = kc * 64;
        // normalize E -> final attn_w, convert to hi/lo bf16 tiles
        for (int i = tid; i < 2048; i += 256) {
            int row = i >> 4, u = i & 15;
            float* ea = attn + ((size_t)n * S + qb + row) * S + k0g + u * 4;
            float4 e = *(float4*)ea;
            float iv = sInv[row];
            e.x *= iv; e.y *= iv; e.z *= iv; e.w *= iv;
            *(float4*)ea = e;
            float ef[4] = {e.x, e.y, e.z, e.w};
            __align__(8) __nv_bfloat16 hb[4], lb[4];
#pragma unroll
            for (int j = 0; j < 4; j++) {
                hb[j] = __float2bfloat16(ef[j]);
                lb[j] = __float2bfloat16(ef[j] - __bfloat162float(hb[j]));
            }
            *(uint2*)(sPh + row * PAD + u * 4) = *(uint2*)hb;
            *(uint2*)(sPl + row * PAD + u * 4) = *(uint2*)lb;
        }
        for (int i = tid; i < 512; i += 256) {
            int cc = i >> 3, u = i & 7;
            size_t off = ((size_t)n * DK + cc) * S + k0g + u * 8;
            *(uint4*)(sVh + cc * PAD + u * 8) = *(const uint4*)(g_Vhi + off);
            *(uint4*)(sVl + cc * PAD + u * 8) = *(const uint4*)(g_Vlo + off);
        }
        __syncthreads();
#pragma unroll
        for (int ks = 0; ks < 4; ks++) {
            const int k0 = ks * 16;
            uint32_t ah[2][4], al[2][4];
#pragma unroll
            for (int mf = 0; mf < 2; mf++) {
                uint32_t off = (uint32_t)((arow + mf * 16) * PAD + k0 + acol8) * 2;
                ldsm4(uPh + off, ah[mf][0], ah[mf][1], ah[mf][2], ah[mf][3]);
                ldsm4(uPl + off, al[mf][0], al[mf][1], al[mf][2], al[mf][3]);
            }
#pragma unroll
            for (int nf2 = 0; nf2 < 2; nf2++) {
                uint32_t boff = (uint32_t)((brow + nf2 * 16) * PAD + k0 + bcol8) * 2;
                uint32_t bh[4], bl[4];
                ldsm4(uVh + boff, bh[0], bh[1], bh[2], bh[3]);
                ldsm4(uVl + boff, bl[0], bl[1], bl[2], bl[3]);
#pragma unroll
                for (int mf = 0; mf < 2; mf++) {
                    float* c0 = acc[mf * 4 + nf2 * 2];
                    float* c1 = acc[mf * 4 + nf2 * 2 + 1];
                    mma16816(c0, ah[mf], bh[0], bh[1]);
                    mma16816(c0, al[mf], bh[0], bh[1]);
                    mma16816(c0, ah[mf], bl[0], bl[1]);
                    mma16816(c1, ah[mf], bh[2], bh[3]);
                    mma16816(c1, al[mf], bh[2], bh[3]);
                    mma16816(c1, ah[mf], bl[2], bl[3]);
                }
            }
        }
        __syncthreads();
    }

    // scatter O into torch-faithful [B,S,DM]
    const int g = lane >> 2, c = lane & 3;
#pragma unroll
    for (int mf = 0; mf < 2; mf++)
#pragma unroll
        for (int nf = 0; nf < 4; nf++) {
            float* a = acc[mf * 4 + nf];
            int col = wn * 32 + nf * 8 + c * 2;
#pragma unroll
            for (int hh = 0; hh < 2; hh++) {
                int q = qb + wm * 32 + mf * 16 + g + hh * 8;
                float* dst = g_AO + ((size_t)(q >> 9) * S + ((q & 511) << 2) + (n >> 3)) * DM +
                             (n & 7) * 64 + col;
                float2 v;
                v.x = a[hh * 2]; v.y = a[hh * 2 + 1];
                *(float2*)dst = v;
            }
        }
}

// ---------------------------------------------------------------------------
// K5: out-projection
// ---------------------------------------------------------------------------
__global__ __launch_bounds__(256) void proj_kernel(
    const float* __restrict__ Wo, const float* __restrict__ bo, float* __restrict__ Z)
{
    const int s0 = blockIdx.x * 64, d0 = blockIdx.y * 64, bp = blockIdx.z;
    __shared__ float sW[64][33];
    __shared__ float sA[64][33];
    const int tid = threadIdx.x, tx = tid & 15, ty = tid >> 4;
    float acc[4][4] = {};
    for (int m0 = 0; m0 < DM; m0 += 32) {
#pragma unroll
        for (int r = 0; r < 2; r++) {
            int row = (tid >> 3) + r * 32, cv = (tid & 7) * 4;
            float4 w4 = *(const float4*)(Wo + (size_t)(d0 + row) * DM + m0 + cv);
            float4 a4 = *(const float4*)(g_AO + ((size_t)bp * S + s0 + row) * DM + m0 + cv);
            sW[row][cv] = w4.x; sW[row][cv + 1] = w4.y; sW[row][cv + 2] = w4.z; sW[row][cv + 3] = w4.w;
            sA[row][cv] = a4.x; sA[row][cv + 1] = a4.y; sA[row][cv + 2] = a4.z; sA[row][cv + 3] = a4.w;
        }
        __syncthreads();
#pragma unroll
        for (int kk = 0; kk < 32; kk++) {
            float a[4], c4[4];
#pragma unroll
            for (int i = 0; i < 4; i++) { a[i] = sW[ty * 4 + i][kk]; c4[i] = sA[tx * 4 + i][kk]; }
#pragma unroll
            for (int i = 0; i < 4; i++)
#pragma unroll
                for (int j = 0; j < 4; j++) acc[i][j] += a[i] * c4[j];
        }
        __syncthreads();
    }
#pragma unroll
    for (int i = 0; i < 4; i++) {
        int d = d0 + ty * 4 + i;
        float bias = bo[d];
        float4 r;
        r.x = acc[i][0] + bias; r.y = acc[i][1] + bias;
        r.z = acc[i][2] + bias; r.w = acc[i][3] + bias;
        *(float4*)(Z + (size_t)(bp * DIN + d) * S + s0 + tx * 4) = r;
    }
}

// ---------------------------------------------------------------------------
extern "C" void kernel_launch(void* const* d_in, const int* in_sizes, int n_in,
                              void* d_out, int out_size)
{
    const float* x  = (const float*)d_in[0];
    const float* Wq = (const float*)d_in[1];
    const float* bq = (const float*)d_in[2];
    const float* Wk = (const float*)d_in[3];
    const float* bk = (const float*)d_in[4];
    const float* Wv = (const float*)d_in[5];
    const float* bv = (const float*)d_in[6];
    const float* Wo = (const float*)d_in[7];
    const float* bo = (const float*)d_in[8];
    float* out = (float*)d_out;

    const long long zsz = (long long)NB * DIN * S;
    const long long asz = (long long)NB * H * S * S;
    float* attn;
    if ((long long)out_size >= zsz + asz) {
        attn = out + zsz;
    } else {
        void* p = nullptr;
        cudaGetSymbolAddress(&p, g_scratch);
        attn = (float*)p;
    }

    const int score_smem = 4 * 128 * PAD * 2;            // 73,728 B
    const int av_smem    = (2 * 128 + 2 * 64) * PAD * 2; // 55,296 B
    cudaFuncSetAttribute(score_kernel, cudaFuncAttributeMaxDynamicSharedMemorySize, score_smem);
    cudaFuncSetAttribute(av_kernel, cudaFuncAttributeMaxDynamicSharedMemorySize, av_smem);

    qkv_kernel<<<dim3(S / 64, DM / 64, NB), 256>>>(x, Wq, bq, Wk, bk, Wv, bv);
    score_kernel<<<dim3(16, 16, BH), 256, score_smem>>>(attn);
    reduce_kernel<<<BH * S / 256, 256>>>();
    av_kernel<<<dim3(16, BH), 256, av_smem>>>(attn);
    proj_kernel<<<dim3(S / 64, DIN / 64, NB), 256>>>(Wo, bo, out);
}

// round 6
// speedup vs baseline: 1.8001x; 1.4361x over previous
#include <cuda_runtime.h>
#include <cuda_bf16.h>
#include <stdint.h>
#include <math.h>

#define S   2048
#define DIN 256
#define DM  512
#define NB  4
#define H   8
#define DK  64
#define BH  32

__device__ __nv_bfloat16 g_Qc[(size_t)BH * S * 128];   // [n][s][hi(64)|lo(64)]
__device__ __nv_bfloat16 g_Kc[(size_t)BH * S * 128];
__device__ __nv_bfloat16 g_Vhi[(size_t)BH * DK * S];   // [n][c][s]
__device__ __nv_bfloat16 g_Vlo[(size_t)BH * DK * S];
__device__ float g_part[(size_t)BH * S * 32];
__device__ float g_inv[(size_t)BH * S];
__device__ float g_AO[(size_t)NB * S * DM];
__device__ float g_scratch[(size_t)NB * H * S * S];

__device__ __forceinline__ uint32_t smem_u32(const void* p) {
    uint32_t a;
    asm("{ .reg .u64 t; cvta.to.shared.u64 t, %1; cvt.u32.u64 %0, t; }" : "=r"(a) : "l"(p));
    return a;
}
__device__ __forceinline__ void ldsm4(uint32_t addr, uint32_t& r0, uint32_t& r1,
                                      uint32_t& r2, uint32_t& r3) {
    asm volatile("ldmatrix.sync.aligned.m8n8.x4.shared.b16 {%0,%1,%2,%3}, [%4];"
                 : "=r"(r0), "=r"(r1), "=r"(r2), "=r"(r3) : "r"(addr));
}
__device__ __forceinline__ void mma16816(float* c, const uint32_t* a, uint32_t b0, uint32_t b1) {
    asm volatile(
        "mma.sync.aligned.m16n8k16.row.col.f32.bf16.bf16.f32 "
        "{%0,%1,%2,%3},{%4,%5,%6,%7},{%8,%9},{%0,%1,%2,%3};"
        : "+f"(c[0]), "+f"(c[1]), "+f"(c[2]), "+f"(c[3])
        : "r"(a[0]), "r"(a[1]), "r"(a[2]), "r"(a[3]), "r"(b0), "r"(b1));
}
__device__ __forceinline__ void cp16(uint32_t s, const void* g) {
    asm volatile("cp.async.cg.shared.global [%0], [%1], 16;" :: "r"(s), "l"(g));
}
#define CP_COMMIT() asm volatile("cp.async.commit_group;" ::: "memory")
#define CP_WAIT0()  asm volatile("cp.async.wait_group 0;" ::: "memory")

// ---------------------------------------------------------------------------
// K1: QKV projection (fp32 SIMT) + bf16 hi/lo emission
// ---------------------------------------------------------------------------
__global__ __launch_bounds__(256) void qkv_kernel(
    const float* __restrict__ x,
    const float* __restrict__ Wq, const float* __restrict__ bq,
    const float* __restrict__ Wk, const float* __restrict__ bk,
    const float* __restrict__ Wv, const float* __restrict__ bv)
{
    const int s0 = blockIdx.x * 64, m0 = blockIdx.y * 64, b = blockIdx.z;
    __shared__ float sX[16][64];
    __shared__ float sW[3][64][16];
    const int tid = threadIdx.x, tx = tid & 15, ty = tid >> 4;
    float acc[3][4][4];
#pragma unroll
    for (int w = 0; w < 3; w++)
#pragma unroll
        for (int i = 0; i < 4; i++)
#pragma unroll
            for (int j = 0; j < 4; j++) acc[w][i][j] = 0.f;

    for (int d0 = 0; d0 < DIN; d0 += 16) {
        {
            int dd = tid >> 4, sv = (tid & 15) * 4;
            *(float4*)&sX[dd][sv] = *(const float4*)(x + (size_t)(b * DIN + d0 + dd) * S + s0 + sv);
        }
        {
            int mm = tid >> 2, dv = (tid & 3) * 4;
            const int wofs = (m0 + mm) * DIN + d0 + dv;
            *(float4*)&sW[0][mm][dv] = *(const float4*)(Wq + wofs);
            *(float4*)&sW[1][mm][dv] = *(const float4*)(Wk + wofs);
            *(float4*)&sW[2][mm][dv] = *(const float4*)(Wv + wofs);
        }
        __syncthreads();
#pragma unroll
        for (int dd = 0; dd < 16; dd++) {
            float xb[4];
            *(float4*)xb = *(float4*)&sX[dd][tx * 4];
#pragma unroll
            for (int w = 0; w < 3; w++) {
                float wr[4];
#pragma unroll
                for (int i = 0; i < 4; i++) wr[i] = sW[w][ty * 4 + i][dd];
#pragma unroll
                for (int i = 0; i < 4; i++)
#pragma unroll
                    for (int j = 0; j < 4; j++) acc[w][i][j] += wr[i] * xb[j];
            }
        }
        __syncthreads();
    }

    const int n = b * 8 + (m0 >> 6);
    const float* bs[3] = {bq, bk, bv};
#pragma unroll
    for (int w = 0; w < 3; w++) {
        float v[4][4];
#pragma unroll
        for (int i = 0; i < 4; i++) {
            float bb = bs[w][m0 + ty * 4 + i];
#pragma unroll
            for (int j = 0; j < 4; j++) v[i][j] = acc[w][i][j] + bb;
        }
        if (w < 2) {
            __nv_bfloat16* dst = (w == 0) ? g_Qc : g_Kc;
#pragma unroll
            for (int j = 0; j < 4; j++) {
                __align__(8) __nv_bfloat16 hi[4], lo[4];
#pragma unroll
                for (int i = 0; i < 4; i++) {
                    float p = v[i][j];
                    hi[i] = __float2bfloat16(p);
                    lo[i] = __float2bfloat16(p - __bfloat162float(hi[i]));
                }
                size_t off = ((size_t)n * S + s0 + tx * 4 + j) * 128 + ty * 4;
                *(uint2*)(dst + off) = *(uint2*)hi;
                *(uint2*)(dst + off + 64) = *(uint2*)lo;
            }
        } else {
#pragma unroll
            for (int i = 0; i < 4; i++) {
                __align__(8) __nv_bfloat16 hi[4], lo[4];
#pragma unroll
                for (int j = 0; j < 4; j++) {
                    float p = v[i][j];
                    hi[j] = __float2bfloat16(p);
                    lo[j] = __float2bfloat16(p - __bfloat162float(hi[j]));
                }
                size_t off = ((size_t)n * DK + ty * 4 + i) * S + s0 + tx * 4;
                *(uint2*)(g_Vhi + off) = *(uint2*)hi;
                *(uint2*)(g_Vlo + off) = *(uint2*)lo;
            }
        }
    }
}

// ---------------------------------------------------------------------------
// K2: scores via mma.sync hi/lo (3 products). Writes exp(S) + partial rowsums.
// ---------------------------------------------------------------------------
#define PAD 72
__global__ __launch_bounds__(256) void score_kernel(float* __restrict__ attn)
{
    extern __shared__ char smp[];
    __nv_bfloat16* sQh = (__nv_bfloat16*)smp;       // [128][PAD]
    __nv_bfloat16* sQl = sQh + 128 * PAD;
    __nv_bfloat16* sKh = sQl + 128 * PAD;
    __nv_bfloat16* sKl = sKh + 128 * PAD;
    const int kb = blockIdx.x * 128, qb = blockIdx.y * 128, n = blockIdx.z;
    const int tid = threadIdx.x, wid = tid >> 5, lane = tid & 31;
    const int wm = wid >> 1, wn = wid & 1;

    const __nv_bfloat16* Qg = g_Qc + ((size_t)n * S + qb) * 128;
    const __nv_bfloat16* Kg = g_Kc + ((size_t)n * S + kb) * 128;
    for (int u = tid; u < 2048; u += 256) {
        int row = u >> 4, ch = u & 15;
        __nv_bfloat16* dq = (ch < 8 ? sQh : sQl) + row * PAD + (ch & 7) * 8;
        __nv_bfloat16* dk = (ch < 8 ? sKh : sKl) + row * PAD + (ch & 7) * 8;
        cp16(smem_u32(dq), Qg + row * 128 + ch * 8);
        cp16(smem_u32(dk), Kg + row * 128 + ch * 8);
    }
    CP_COMMIT();
    CP_WAIT0();
    __syncthreads();

    float acc[16][4];
#pragma unroll
    for (int f = 0; f < 16; f++)
#pragma unroll
        for (int e = 0; e < 4; e++) acc[f][e] = 0.f;

    const uint32_t uQh = smem_u32(sQh), uQl = smem_u32(sQl);
    const uint32_t uKh = smem_u32(sKh), uKl = smem_u32(sKl);
    const int arow = wm * 32 + (lane & 15);
    const int acol8 = (lane >> 4) << 3;
    const int brow = wn * 64 + (lane & 7) + ((lane >> 4) << 3);
    const int bcol8 = ((lane >> 3) & 1) << 3;

#pragma unroll
    for (int ks = 0; ks < 4; ks++) {
        const int k0 = ks * 16;
        uint32_t ah[2][4], al[2][4];
#pragma unroll
        for (int mf = 0; mf < 2; mf++) {
            uint32_t off = (uint32_t)((arow + mf * 16) * PAD + k0 + acol8) * 2;
            ldsm4(uQh + off, ah[mf][0], ah[mf][1], ah[mf][2], ah[mf][3]);
            ldsm4(uQl + off, al[mf][0], al[mf][1], al[mf][2], al[mf][3]);
        }
#pragma unroll
        for (int nf2 = 0; nf2 < 4; nf2++) {
            uint32_t boff = (uint32_t)((brow + nf2 * 16) * PAD + k0 + bcol8) * 2;
            uint32_t bh[4], bl[4];
            ldsm4(uKh + boff, bh[0], bh[1], bh[2], bh[3]);
            ldsm4(uKl + boff, bl[0], bl[1], bl[2], bl[3]);
#pragma unroll
            for (int mf = 0; mf < 2; mf++) {
                float* c0 = acc[mf * 8 + nf2 * 2];
                float* c1 = acc[mf * 8 + nf2 * 2 + 1];
                mma16816(c0, ah[mf], bh[0], bh[1]);
                mma16816(c0, al[mf], bh[0], bh[1]);
                mma16816(c0, ah[mf], bl[0], bl[1]);
                mma16816(c1, ah[mf], bh[2], bh[3]);
                mma16816(c1, al[mf], bh[2], bh[3]);
                mma16816(c1, ah[mf], bl[2], bl[3]);
            }
        }
    }
    __syncthreads();

    float* sS = (float*)smp;  // [128][132]
    const int g = lane >> 2, c = lane & 3;
    float rsum[4] = {0.f, 0.f, 0.f, 0.f};
#pragma unroll
    for (int mf = 0; mf < 2; mf++)
#pragma unroll
        for (int nf = 0; nf < 8; nf++) {
            float* a = acc[mf * 8 + nf];
            int r0 = wm * 32 + mf * 16 + g, col = wn * 64 + nf * 8 + c * 2;
            float e0 = __expf(a[0]), e1 = __expf(a[1]);
            float e2 = __expf(a[2]), e3 = __expf(a[3]);
            sS[r0 * 132 + col] = e0;       sS[r0 * 132 + col + 1] = e1;
            sS[(r0 + 8) * 132 + col] = e2; sS[(r0 + 8) * 132 + col + 1] = e3;
            rsum[mf * 2] += e0 + e1;
            rsum[mf * 2 + 1] += e2 + e3;
        }
#pragma unroll
    for (int off = 1; off <= 2; off <<= 1)
#pragma unroll
        for (int i = 0; i < 4; i++) rsum[i] += __shfl_xor_sync(0xffffffffu, rsum[i], off);
    if (c == 0) {
#pragma unroll
        for (int mf = 0; mf < 2; mf++)
#pragma unroll
            for (int hh = 0; hh < 2; hh++) {
                int r = wm * 32 + mf * 16 + g + hh * 8;
                g_part[((size_t)n * S + qb + r) * 32 + blockIdx.x * 2 + wn] = rsum[mf * 2 + hh];
            }
    }
    __syncthreads();
    for (int it = tid; it < 4096; it += 256) {
        int row = it >> 5, c4 = it & 31;
        __stcs((float4*)(attn + ((size_t)n * S + qb + row) * S + kb + c4 * 4),
               *(float4*)(sS + row * 132 + c4 * 4));
    }
}

// ---------------------------------------------------------------------------
// K3: rowsum reduce -> inverse
// ---------------------------------------------------------------------------
__global__ __launch_bounds__(256) void reduce_kernel()
{
    int row = blockIdx.x * 256 + threadIdx.x;
    const float* p = g_part + (size_t)row * 32;
    float s = 0.f;
#pragma unroll
    for (int i = 0; i < 32; i++) s += p[i];
    g_inv[row] = 1.f / s;
}

// ---------------------------------------------------------------------------
// K4 helper: normalize E regs -> streaming attn_w store + hi/lo SMEM tiles
// ---------------------------------------------------------------------------
__device__ __forceinline__ void conv_chunk(
    const float4* e, float* attnC, int r0, int u, const float* sInv,
    __nv_bfloat16* Ph, __nv_bfloat16* Pl)
{
#pragma unroll
    for (int i = 0; i < 8; i++) {
        int row = r0 + i * 16;
        float iv = sInv[row];
        float4 v = e[i];
        v.x *= iv; v.y *= iv; v.z *= iv; v.w *= iv;
        __stcs((float4*)(attnC + (size_t)row * S + u * 4), v);
        float ef[4] = {v.x, v.y, v.z, v.w};
        __align__(8) __nv_bfloat16 hb[4], lb[4];
#pragma unroll
        for (int j = 0; j < 4; j++) {
            hb[j] = __float2bfloat16(ef[j]);
            lb[j] = __float2bfloat16(ef[j] - __bfloat162float(hb[j]));
        }
        *(uint2*)(Ph + row * PAD + u * 4) = *(uint2*)hb;
        *(uint2*)(Pl + row * PAD + u * 4) = *(uint2*)lb;
    }
}

// ---------------------------------------------------------------------------
// K4: pipelined AV: prefetch E(kc+1)/V(kc+1) -> MMA(kc) -> convert -> 1 sync.
// ---------------------------------------------------------------------------
__global__ __launch_bounds__(256) void av_kernel(float* __restrict__ attn)
{
    extern __shared__ char smp[];
    __nv_bfloat16* sPh = (__nv_bfloat16*)smp;         // [2][128*PAD]
    __nv_bfloat16* sPl = sPh + 2 * 128 * PAD;
    __nv_bfloat16* sVh = sPl + 2 * 128 * PAD;         // [2][64*PAD]
    __nv_bfloat16* sVl = sVh + 2 * 64 * PAD;
    __shared__ float sInv[128];
    const int qb = blockIdx.x * 128, n = blockIdx.y;
    const int tid = threadIdx.x, wid = tid >> 5, lane = tid & 31;
    const int wm = wid >> 1, wn = wid & 1;
    const int r0 = tid >> 4, u = tid & 15;
    if (tid < 128) sInv[tid] = g_inv[(size_t)n * S + qb + tid];
    __syncthreads();

    float* attnBase = attn + ((size_t)n * S + qb) * S;
    const __nv_bfloat16* Vh = g_Vhi + (size_t)n * DK * S;
    const __nv_bfloat16* Vl = g_Vlo + (size_t)n * DK * S;

    // prologue: chunk 0
    float4 e[8];
#pragma unroll
    for (int i = 0; i < 8; i++)
        e[i] = __ldcs((const float4*)(attnBase + (size_t)(r0 + i * 16) * S + u * 4));
#pragma unroll
    for (int j = 0; j < 2; j++) {
        int idx = tid + j * 256, cc = idx >> 3, uu = idx & 7;
        size_t go = (size_t)cc * S + uu * 8;
        cp16(smem_u32(sVh + cc * PAD + uu * 8), Vh + go);
        cp16(smem_u32(sVl + cc * PAD + uu * 8), Vl + go);
    }
    CP_COMMIT();
    conv_chunk(e, attnBase, r0, u, sInv, sPh, sPl);
    CP_WAIT0();
    __syncthreads();

    float acc[8][4];
#pragma unroll
    for (int f = 0; f < 8; f++)
#pragma unroll
        for (int ee = 0; ee < 4; ee++) acc[f][ee] = 0.f;

    const int arow = wm * 32 + (lane & 15);
    const int acol8 = (lane >> 4) << 3;
    const int brow = wn * 32 + (lane & 7) + ((lane >> 4) << 3);
    const int bcol8 = ((lane >> 3) & 1) << 3;

    for (int kc = 0; kc < 32; kc++) {
        const int buf = kc & 1, nxt = buf ^ 1;
        if (kc < 31) {
            float* aC = attnBase + (kc + 1) * 64;
#pragma unroll
            for (int i = 0; i < 8; i++)
                e[i] = __ldcs((const float4*)(aC + (size_t)(r0 + i * 16) * S + u * 4));
#pragma unroll
            for (int j = 0; j < 2; j++) {
                int idx = tid + j * 256, cc = idx >> 3, uu = idx & 7;
                size_t go = (size_t)cc * S + (kc + 1) * 64 + uu * 8;
                cp16(smem_u32(sVh + nxt * 64 * PAD + cc * PAD + uu * 8), Vh + go);
                cp16(smem_u32(sVl + nxt * 64 * PAD + cc * PAD + uu * 8), Vl + go);
            }
            CP_COMMIT();
        }
        // MMA on buffer `buf`
        const uint32_t uPh = smem_u32(sPh + buf * 128 * PAD);
        const uint32_t uPl = smem_u32(sPl + buf * 128 * PAD);
        const uint32_t uVh = smem_u32(sVh + buf * 64 * PAD);
        const uint32_t uVl = smem_u32(sVl + buf * 64 * PAD);
#pragma unroll
        for (int ks = 0; ks < 4; ks++) {
            const int k0 = ks * 16;
            uint32_t ah[2][4], al[2][4];
#pragma unroll
            for (int mf = 0; mf < 2; mf++) {
                uint32_t off = (uint32_t)((arow + mf * 16) * PAD + k0 + acol8) * 2;
                ldsm4(uPh + off, ah[mf][0], ah[mf][1], ah[mf][2], ah[mf][3]);
                ldsm4(uPl + off, al[mf][0], al[mf][1], al[mf][2], al[mf][3]);
            }
#pragma unroll
            for (int nf2 = 0; nf2 < 2; nf2++) {
                uint32_t boff = (uint32_t)((brow + nf2 * 16) * PAD + k0 + bcol8) * 2;
                uint32_t bh[4], bl[4];
                ldsm4(uVh + boff, bh[0], bh[1], bh[2], bh[3]);
                ldsm4(uVl + boff, bl[0], bl[1], bl[2], bl[3]);
#pragma unroll
                for (int mf = 0; mf < 2; mf++) {
                    float* c0 = acc[mf * 4 + nf2 * 2];
                    float* c1 = acc[mf * 4 + nf2 * 2 + 1];
                    mma16816(c0, ah[mf], bh[0], bh[1]);
                    mma16816(c0, al[mf], bh[0], bh[1]);
                    mma16816(c0, ah[mf], bl[0], bl[1]);
                    mma16816(c1, ah[mf], bh[2], bh[3]);
                    mma16816(c1, al[mf], bh[2], bh[3]);
                    mma16816(c1, ah[mf], bl[2], bl[3]);
                }
            }
        }
        if (kc < 31) {
            conv_chunk(e, attnBase + (kc + 1) * 64, r0, u, sInv,
                       sPh + nxt * 128 * PAD, sPl + nxt * 128 * PAD);
            CP_WAIT0();
        }
        __syncthreads();
    }

    // scatter O into torch-faithful [B,S,DM]
    const int g = lane >> 2, c = lane & 3;
#pragma unroll
    for (int mf = 0; mf < 2; mf++)
#pragma unroll
        for (int nf = 0; nf < 4; nf++) {
            float* a = acc[mf * 4 + nf];
            int col = wn * 32 + nf * 8 + c * 2;
#pragma unroll
            for (int hh = 0; hh < 2; hh++) {
                int q = qb + wm * 32 + mf * 16 + g + hh * 8;
                float* dst = g_AO + ((size_t)(q >> 9) * S + ((q & 511) << 2) + (n >> 3)) * DM +
                             (n & 7) * 64 + col;
                float2 v;
                v.x = a[hh * 2]; v.y = a[hh * 2 + 1];
                *(float2*)dst = v;
            }
        }
}

// ---------------------------------------------------------------------------
// K5: out-projection
// ---------------------------------------------------------------------------
__global__ __launch_bounds__(256) void proj_kernel(
    const float* __restrict__ Wo, const float* __restrict__ bo, float* __restrict__ Z)
{
    const int s0 = blockIdx.x * 64, d0 = blockIdx.y * 64, bp = blockIdx.z;
    __shared__ float sW[64][33];
    __shared__ float sA[64][33];
    const int tid = threadIdx.x, tx = tid & 15, ty = tid >> 4;
    float acc[4][4] = {};
    for (int m0 = 0; m0 < DM; m0 += 32) {
#pragma unroll
        for (int r = 0; r < 2; r++) {
            int row = (tid >> 3) + r * 32, cv = (tid & 7) * 4;
            float4 w4 = *(const float4*)(Wo + (size_t)(d0 + row) * DM + m0 + cv);
            float4 a4 = *(const float4*)(g_AO + ((size_t)bp * S + s0 + row) * DM + m0 + cv);
            sW[row][cv] = w4.x; sW[row][cv + 1] = w4.y; sW[row][cv + 2] = w4.z; sW[row][cv + 3] = w4.w;
            sA[row][cv] = a4.x; sA[row][cv + 1] = a4.y; sA[row][cv + 2] = a4.z; sA[row][cv + 3] = a4.w;
        }
        __syncthreads();
#pragma unroll
        for (int kk = 0; kk < 32; kk++) {
            float a[4], c4[4];
#pragma unroll
            for (int i = 0; i < 4; i++) { a[i] = sW[ty * 4 + i][kk]; c4[i] = sA[tx * 4 + i][kk]; }
#pragma unroll
            for (int i = 0; i < 4; i++)
#pragma unroll
                for (int j = 0; j < 4; j++) acc[i][j] += a[i] * c4[j];
        }
        __syncthreads();
    }
#pragma unroll
    for (int i = 0; i < 4; i++) {
        int d = d0 + ty * 4 + i;
        float bias = bo[d];
        float4 r;
        r.x = acc[i][0] + bias; r.y = acc[i][1] + bias;
        r.z = acc[i][2] + bias; r.w = acc[i][3] + bias;
        *(float4*)(Z + (size_t)(bp * DIN + d) * S + s0 + tx * 4) = r;
    }
}

// ---------------------------------------------------------------------------
extern "C" void kernel_launch(void* const* d_in, const int* in_sizes, int n_in,
                              void* d_out, int out_size)
{
    const float* x  = (const float*)d_in[0];
    const float* Wq = (const float*)d_in[1];
    const float* bq = (const float*)d_in[2];
    const float* Wk = (const float*)d_in[3];
    const float* bk = (const float*)d_in[4];
    const float* Wv = (const float*)d_in[5];
    const float* bv = (const float*)d_in[6];
    const float* Wo = (const float*)d_in[7];
    const float* bo = (const float*)d_in[8];
    float* out = (float*)d_out;

    const long long zsz = (long long)NB * DIN * S;
    const long long asz = (long long)NB * H * S * S;
    float* attn;
    if ((long long)out_size >= zsz + asz) {
        attn = out + zsz;
    } else {
        void* p = nullptr;
        cudaGetSymbolAddress(&p, g_scratch);
        attn = (float*)p;
    }

    const int score_smem = 4 * 128 * PAD * 2;                    // 73,728 B
    const int av_smem    = 2 * (2 * 128 + 2 * 64) * PAD * 2;     // 110,592 B
    cudaFuncSetAttribute(score_kernel, cudaFuncAttributeMaxDynamicSharedMemorySize, score_smem);
    cudaFuncSetAttribute(av_kernel, cudaFuncAttributeMaxDynamicSharedMemorySize, av_smem);

    qkv_kernel<<<dim3(S / 64, DM / 64, NB), 256>>>(x, Wq, bq, Wk, bk, Wv, bv);
    score_kernel<<<dim3(16, 16, BH), 256, score_smem>>>(attn);
    reduce_kernel<<<BH * S / 256, 256>>>();
    av_kernel<<<dim3(16, BH), 256, av_smem>>>(attn);
    proj_kernel<<<dim3(S / 64, DIN / 64, NB), 256>>>(Wo, bo, out);
}